// round 14
// baseline (speedup 1.0000x reference)
#include <cuda_runtime.h>
#include <cuda_fp16.h>
#include <math.h>
#include <stdint.h>
#include <string.h>

// ---------------------------------------------------------------------------
// MoE grouped MLP via fp16 mma.sync m16n8k16, BK=64 stages (halved barriers).
// GEMM1: 128x64(x2 mats), 256 thr, 2 CTA/SM.  GEMM2: 128x128, 256 thr.
// T=4096 H=2048 I=1408 E=8 K=2; rows = 8192.
// ---------------------------------------------------------------------------
#define T_TOK 4096
#define H_DIM 2048
#define I_DIM 1408
#define N_EXP 8
#define TOPK  2
#define R_ROWS (T_TOK * TOPK)
#define BM 128
#define MAX_TILES (R_ROWS / BM + N_EXP)   // 72

#define BK 64
#define STAGES 3
#define NK1 (H_DIM / BK)                   // 32
#define NK2 (I_DIM / BK)                   // 22

#define BN1 64
#define BN2 128

// A-tile SMEM: 128 rows x 64 halfs, padded stride 72 halfs (conflict-free)
#define SH 72
#define AS_H (BM * SH)                     // 9216 halfs = 18432 B
#define BT1_B (BK * BN1 * 2)               // 8192 B  (per matrix)
#define BT2_B (BK * BN2 * 2)               // 16384 B
#define G1_SMEM (STAGES * (AS_H * 2 + 2 * BT1_B))   // 104448 B
#define G2_SMEM (STAGES * (AS_H * 2 + BT2_B))       // 104448 B

#define XP_ROWS  (R_ROWS + 128)
#define ACT_ROWS (R_ROWS + 128)

// static scaling: x*64, W*64, act*4096
#define S_IN   64.0f
#define DESC1  (1.0f / (64.0f * 64.0f))
#define S_ACT  4096.0f
#define DESC2  (1.0f / (4096.0f * 64.0f))

// ---- device-global scratch ----
__device__ int    g_counts[N_EXP];
__device__ int    g_cursor[N_EXP];
__device__ int    g_tile_e[MAX_TILES];
__device__ int    g_tile_row0[MAX_TILES];
__device__ int    g_tile_rows[MAX_TILES];
__device__ int    g_num_tiles;
__device__ int    g_row_t[R_ROWS];
__device__ float  g_row_p[R_ROWS];
__device__ __half g_xp[(size_t)XP_ROWS * H_DIM];
__device__ __half g_act[(size_t)ACT_ROWS * I_DIM];
__device__ __half g_gate_h[(size_t)N_EXP * H_DIM * I_DIM];   // [E][H][I]
__device__ __half g_up_h  [(size_t)N_EXP * H_DIM * I_DIM];
__device__ __half g_down_h[(size_t)N_EXP * I_DIM * H_DIM];   // [E][I][H]

// ---------------------------------------------------------------------------
__device__ __forceinline__ uint32_t h2_bits(__half2 h) {
    uint32_t u;
    memcpy(&u, &h, 4);
    return u;
}
__device__ __forceinline__ void cp16(void* dst, const void* src) {
    uint32_t d = (uint32_t)__cvta_generic_to_shared(dst);
    asm volatile("cp.async.cg.shared.global [%0], [%1], 16;" :: "r"(d), "l"(src) : "memory");
}
__device__ __forceinline__ void cp16s(uint32_t dst, const void* src) {
    asm volatile("cp.async.cg.shared.global [%0], [%1], 16;" :: "r"(dst), "l"(src) : "memory");
}
#define CP_COMMIT() asm volatile("cp.async.commit_group;" ::: "memory")
#define CP_WAIT1()  asm volatile("cp.async.wait_group 1;" ::: "memory")

#define MMA_F16(d, a, b0, b1)                                                \
    asm volatile("mma.sync.aligned.m16n8k16.row.col.f32.f16.f16.f32 "        \
        "{%0,%1,%2,%3}, {%4,%5,%6,%7}, {%8,%9}, {%0,%1,%2,%3};"              \
        : "+f"((d)[0]), "+f"((d)[1]), "+f"((d)[2]), "+f"((d)[3])             \
        : "r"((a)[0]), "r"((a)[1]), "r"((a)[2]), "r"((a)[3]),                \
          "r"(b0), "r"(b1))

#define LDSM4(r, addr)                                                        \
    asm volatile("ldmatrix.sync.aligned.m8n8.x4.shared.b16 {%0,%1,%2,%3}, [%4];" \
        : "=r"((r)[0]), "=r"((r)[1]), "=r"((r)[2]), "=r"((r)[3]) : "r"(addr))

#define LDSM4T(r, addr)                                                       \
    asm volatile("ldmatrix.sync.aligned.m8n8.x4.trans.shared.b16 {%0,%1,%2,%3}, [%4];" \
        : "=r"((r)[0]), "=r"((r)[1]), "=r"((r)[2]), "=r"((r)[3]) : "r"(addr))

#define REDV2(ptr, v0, v1)                                                    \
    asm volatile("red.global.add.v2.f32 [%0], {%1, %2};"                      \
        :: "l"(ptr), "f"(v0), "f"(v1) : "memory")

// ---------------------------------------------------------------------------
// prep kernels
// ---------------------------------------------------------------------------
__global__ void k_zero_counts() { if (threadIdx.x < N_EXP) g_counts[threadIdx.x] = 0; }

__global__ void k_hist(const int* __restrict__ sel) {
    int f = blockIdx.x * blockDim.x + threadIdx.x;
    if (f < R_ROWS) {
        int t = f % T_TOK, k = f / T_TOK;
        atomicAdd(&g_counts[sel[t * TOPK + k]], 1);
    }
}

__global__ void k_prep() {
    int off = 0, nt = 0;
    for (int e = 0; e < N_EXP; ++e) {
        int c = g_counts[e];
        g_cursor[e] = off;
        for (int r0 = 0; r0 < c; r0 += BM) {
            g_tile_e[nt] = e; g_tile_row0[nt] = off + r0;
            g_tile_rows[nt] = min(BM, c - r0); ++nt;
        }
        off += c;
    }
    g_num_tiles = nt;
}

__global__ void k_scatter(const int* __restrict__ sel, const float* __restrict__ rw) {
    int f = blockIdx.x * blockDim.x + threadIdx.x;
    if (f < R_ROWS) {
        int t = f % T_TOK, k = f / T_TOK;
        int e = sel[t * TOPK + k];
        int d = atomicAdd(&g_cursor[e], 1);
        g_row_t[d] = t;
        g_row_p[d] = rw[t * TOPK + k];
    }
}

__global__ void k_zero_out(float4* __restrict__ out, int n4) {
    int i = blockIdx.x * blockDim.x + threadIdx.x;
    if (i < n4) out[i] = make_float4(0.f, 0.f, 0.f, 0.f);
}

// gather rows, scale by 64, convert fp16, 16B stores
__global__ void k_permute(const float* __restrict__ hid) {
    int r = blockIdx.x;
    int t = g_row_t[r];
    const float4* src = (const float4*)(hid + (size_t)t * H_DIM);
    uint4* dst = (uint4*)(g_xp + (size_t)r * H_DIM);
    for (int i = threadIdx.x; i < H_DIM / 8; i += blockDim.x) {
        float4 v0 = src[2 * i], v1 = src[2 * i + 1];
        uint4 o;
        o.x = h2_bits(__floats2half2_rn(v0.x * S_IN, v0.y * S_IN));
        o.y = h2_bits(__floats2half2_rn(v0.z * S_IN, v0.w * S_IN));
        o.z = h2_bits(__floats2half2_rn(v1.x * S_IN, v1.y * S_IN));
        o.w = h2_bits(__floats2half2_rn(v1.z * S_IN, v1.w * S_IN));
        dst[i] = o;
    }
}

// straight streaming convert: out[i] = half(in[i] * S_IN), 8 elems/thread
__global__ void k_convert(const float* __restrict__ in, __half* __restrict__ out,
                          size_t n8) {
    size_t i = (size_t)blockIdx.x * blockDim.x + threadIdx.x;
    if (i < n8) {
        const float4* src = (const float4*)in + 2 * i;
        float4 v0 = src[0], v1 = src[1];
        uint4 o;
        o.x = h2_bits(__floats2half2_rn(v0.x * S_IN, v0.y * S_IN));
        o.y = h2_bits(__floats2half2_rn(v0.z * S_IN, v0.w * S_IN));
        o.z = h2_bits(__floats2half2_rn(v1.x * S_IN, v1.y * S_IN));
        o.w = h2_bits(__floats2half2_rn(v1.z * S_IN, v1.w * S_IN));
        ((uint4*)out)[i] = o;
    }
}

// ---------------------------------------------------------------------------
// GEMM1: act = silu(xp @ gate^T) * (xp @ up^T)
// 128x64 tiles, BK=64 stages, 256 threads = 8 warps (4M x 2N), 32x32 x2 mats.
// ---------------------------------------------------------------------------
__global__ __launch_bounds__(256, 2)
void k_gemm1_mma(const __half* __restrict__ xp,
                 const __half* __restrict__ gt,
                 const __half* __restrict__ ut) {
    const int tile = blockIdx.x;
    if (tile >= g_num_tiles) return;
    const int e    = g_tile_e[tile];
    const int row0 = g_tile_row0[tile];
    const int rows = g_tile_rows[tile];
    const int n0   = blockIdx.y * BN1;

    extern __shared__ __half sm[];
    __half* As = sm;
    const uint32_t su  = (uint32_t)__cvta_generic_to_shared(sm);
    const uint32_t bgu = su + STAGES * AS_H * 2;
    const uint32_t buu = bgu + STAGES * BT1_B;

    const int tid  = threadIdx.x;
    const int lane = tid & 31, wid = tid >> 5;
    const int wm = wid & 3, wn = wid >> 2;
    const int lg = lane >> 2, lt = lane & 3;

    const uint32_t aoff = (((lane & 7) + ((lane >> 3) & 1) * 8) * SH + (lane >> 4) * 8) * 2;
    const uint32_t blk_row  = (lane & 7) + ((lane >> 3) & 1) * 8;
    const uint32_t bxor     = lane & 7;
    const uint32_t bnc_base = wn * 4 + (lane >> 4);

    const __half* arow = xp + (size_t)row0 * H_DIM;
    const __half* gte  = gt + (size_t)e * H_DIM * I_DIM + n0;
    const __half* ute  = ut + (size_t)e * H_DIM * I_DIM + n0;

    // loaders: A 4 cp16/thread (128 rows x 8 chunks), B 2 cp16/thread/matrix
    const int alr = tid >> 1, alc = (tid & 1) * 4;
    const int bk  = tid >> 2, bc2 = (tid & 3) * 2;

    float accg[2][4][4], accu[2][4][4];
    #pragma unroll
    for (int a = 0; a < 2; ++a)
        #pragma unroll
        for (int b = 0; b < 4; ++b)
            #pragma unroll
            for (int c = 0; c < 4; ++c) { accg[a][b][c] = 0.f; accu[a][b][c] = 0.f; }

    #define G1_LOAD(s, ki) do {                                                    \
        int k0_ = (ki) * BK;                                                       \
        __half* as_ = As + (s) * AS_H;                                             \
        _Pragma("unroll")                                                          \
        for (int j = 0; j < 4; ++j)                                                \
            cp16(&as_[alr * SH + (alc + j) * 8],                                   \
                 arow + (size_t)alr * H_DIM + k0_ + (alc + j) * 8);                \
        _Pragma("unroll")                                                          \
        for (int j = 0; j < 2; ++j) {                                              \
            uint32_t sw_ = (uint32_t)(bk * 128 + (((bc2 + j) ^ (bk & 7)) << 4));   \
            cp16s(bgu + (s) * BT1_B + sw_, gte + (size_t)(k0_ + bk) * I_DIM + (bc2 + j) * 8); \
            cp16s(buu + (s) * BT1_B + sw_, ute + (size_t)(k0_ + bk) * I_DIM + (bc2 + j) * 8); \
        }                                                                          \
    } while (0)

    G1_LOAD(0, 0); CP_COMMIT();
    G1_LOAD(1, 1); CP_COMMIT();

    int slot = 0;
    #pragma unroll 1
    for (int ki = 0; ki < NK1; ++ki) {
        CP_WAIT1();
        __syncthreads();
        if (ki + 2 < NK1) {
            int ns = slot + 2; if (ns >= STAGES) ns -= STAGES;
            G1_LOAD(ns, ki + 2);
        }
        CP_COMMIT();

        const uint32_t asb = su  + slot * AS_H * 2 + (wm * 32) * SH * 2 + aoff;
        const uint32_t bgs = bgu + slot * BT1_B;
        const uint32_t bus = buu + slot * BT1_B;
        #pragma unroll
        for (int ks = 0; ks < 4; ++ks) {
            const uint32_t kb2 = ks * 32;   // ks*16 halfs in bytes
            const uint32_t bkrow = (ks * 16 + blk_row) * 128;
            uint32_t af[2][4], bgr[8], bur[8];
            LDSM4(af[0], asb + kb2);
            LDSM4(af[1], asb + 16 * SH * 2 + kb2);
            LDSM4T(&bgr[0], bgs + bkrow + (((bnc_base + 0) ^ bxor) << 4));
            LDSM4T(&bgr[4], bgs + bkrow + (((bnc_base + 2) ^ bxor) << 4));
            LDSM4T(&bur[0], bus + bkrow + (((bnc_base + 0) ^ bxor) << 4));
            LDSM4T(&bur[4], bus + bkrow + (((bnc_base + 2) ^ bxor) << 4));
            #pragma unroll
            for (int nt = 0; nt < 4; ++nt) {
                #pragma unroll
                for (int mt = 0; mt < 2; ++mt) {
                    MMA_F16(accg[mt][nt], af[mt], bgr[2 * nt], bgr[2 * nt + 1]);
                    MMA_F16(accu[mt][nt], af[mt], bur[2 * nt], bur[2 * nt + 1]);
                }
            }
        }
        if (++slot == STAGES) slot = 0;
    }
    #undef G1_LOAD

    // epilogue: descale, silu(g)*u, rescale, store fp16
    #pragma unroll
    for (int mt = 0; mt < 2; ++mt) {
        #pragma unroll
        for (int half = 0; half < 2; ++half) {
            int m = wm * 32 + mt * 16 + lg + half * 8;
            if (m < rows) {
                __half* dst = g_act + (size_t)(row0 + m) * I_DIM + n0 + wn * 32;
                #pragma unroll
                for (int nt = 0; nt < 4; ++nt) {
                    float g0 = accg[mt][nt][half * 2 + 0] * DESC1;
                    float u0 = accu[mt][nt][half * 2 + 0] * DESC1;
                    float g1 = accg[mt][nt][half * 2 + 1] * DESC1;
                    float u1 = accu[mt][nt][half * 2 + 1] * DESC1;
                    float a0 = (g0 / (1.f + __expf(-g0))) * u0 * S_ACT;
                    float a1 = (g1 / (1.f + __expf(-g1))) * u1 * S_ACT;
                    *(__half2*)(dst + nt * 8 + 2 * lt) = __floats2half2_rn(a0, a1);
                }
            }
        }
    }
}

// ---------------------------------------------------------------------------
// GEMM2: out[t] += p * descale * (act @ down^T)
// 128x128 tiles, BK=64 stages, 256 threads = 8 warps (4M x 2N), 32x64 warp.
// ---------------------------------------------------------------------------
__global__ __launch_bounds__(256, 2)
void k_gemm2_mma(const __half* __restrict__ act,
                 const __half* __restrict__ dt,
                 float* __restrict__ out) {
    const int tile = blockIdx.x;
    if (tile >= g_num_tiles) return;
    const int e    = g_tile_e[tile];
    const int row0 = g_tile_row0[tile];
    const int rows = g_tile_rows[tile];
    const int n0   = blockIdx.y * BN2;

    extern __shared__ __half sm[];
    __half* As = sm;
    const uint32_t su  = (uint32_t)__cvta_generic_to_shared(sm);
    const uint32_t bsu = su + STAGES * AS_H * 2;

    const int tid  = threadIdx.x;
    const int lane = tid & 31, wid = tid >> 5;
    const int wm = wid & 3, wn = wid >> 2;       // 4M x 2N
    const int lg = lane >> 2, lt = lane & 3;

    const uint32_t aoff = (((lane & 7) + ((lane >> 3) & 1) * 8) * SH + (lane >> 4) * 8) * 2;
    const uint32_t blk_row  = (lane & 7) + ((lane >> 3) & 1) * 8;
    const uint32_t bxor     = lane & 7;
    const uint32_t bnc_base = wn * 8 + (lane >> 4);   // warp covers 8 chunks (64 cols)

    const __half* arow = act + (size_t)row0 * I_DIM;
    const __half* dte  = dt + (size_t)e * I_DIM * H_DIM + n0;

    const int alr = tid >> 1, alc = (tid & 1) * 4;   // A: 4 cp16/thread
    const int bk  = tid >> 2, bc4 = (tid & 3) * 4;   // B: 4 cp16/thread (16 chunks/row)

    float acc[2][8][4];
    #pragma unroll
    for (int a = 0; a < 2; ++a)
        #pragma unroll
        for (int b = 0; b < 8; ++b)
            #pragma unroll
            for (int c = 0; c < 4; ++c) acc[a][b][c] = 0.f;

    #define G2_LOAD(s, ki) do {                                                    \
        int k0_ = (ki) * BK;                                                       \
        __half* as_ = As + (s) * AS_H;                                             \
        _Pragma("unroll")                                                          \
        for (int j = 0; j < 4; ++j)                                                \
            cp16(&as_[alr * SH + (alc + j) * 8],                                   \
                 arow + (size_t)alr * I_DIM + k0_ + (alc + j) * 8);                \
        _Pragma("unroll")                                                          \
        for (int j = 0; j < 4; ++j) {                                              \
            uint32_t sw_ = (uint32_t)(bk * 256 + (((bc4 + j) ^ (bk & 7)) << 4));   \
            cp16s(bsu + (s) * BT2_B + sw_, dte + (size_t)(k0_ + bk) * H_DIM + (bc4 + j) * 8); \
        }                                                                          \
    } while (0)

    G2_LOAD(0, 0); CP_COMMIT();
    G2_LOAD(1, 1); CP_COMMIT();

    int slot = 0;
    #pragma unroll 1
    for (int ki = 0; ki < NK2; ++ki) {
        CP_WAIT1();
        __syncthreads();
        if (ki + 2 < NK2) {
            int ns = slot + 2; if (ns >= STAGES) ns -= STAGES;
            G2_LOAD(ns, ki + 2);
        }
        CP_COMMIT();

        const uint32_t asb = su  + slot * AS_H * 2 + (wm * 32) * SH * 2 + aoff;
        const uint32_t bss = bsu + slot * BT2_B;
        #pragma unroll
        for (int ks = 0; ks < 4; ++ks) {
            const uint32_t kb2 = ks * 32;
            const uint32_t bkrow = (ks * 16 + blk_row) * 256;
            uint32_t af[2][4], br[16];
            LDSM4(af[0], asb + kb2);
            LDSM4(af[1], asb + 16 * SH * 2 + kb2);
            LDSM4T(&br[0],  bss + bkrow + (((bnc_base + 0) ^ bxor) << 4));
            LDSM4T(&br[4],  bss + bkrow + (((bnc_base + 2) ^ bxor) << 4));
            LDSM4T(&br[8],  bss + bkrow + (((bnc_base + 4) ^ bxor) << 4));
            LDSM4T(&br[12], bss + bkrow + (((bnc_base + 6) ^ bxor) << 4));
            #pragma unroll
            for (int nt = 0; nt < 8; ++nt) {
                #pragma unroll
                for (int mt = 0; mt < 2; ++mt)
                    MMA_F16(acc[mt][nt], af[mt], br[2 * nt], br[2 * nt + 1]);
            }
        }
        if (++slot == STAGES) slot = 0;
    }
    #undef G2_LOAD

    // epilogue: weighted vector reduce-add with descale
    #pragma unroll
    for (int mt = 0; mt < 2; ++mt) {
        #pragma unroll
        for (int half = 0; half < 2; ++half) {
            int m = wm * 32 + mt * 16 + lg + half * 8;
            if (m < rows) {
                float p = g_row_p[row0 + m] * DESC2;
                int   t = g_row_t[row0 + m];
                float* dst = out + (size_t)t * H_DIM + n0 + wn * 64;
                #pragma unroll
                for (int nt = 0; nt < 8; ++nt) {
                    REDV2(dst + nt * 8 + 2 * lt,
                          acc[mt][nt][half * 2 + 0] * p,
                          acc[mt][nt][half * 2 + 1] * p);
                }
            }
        }
    }
}

// ---------------------------------------------------------------------------
extern "C" void kernel_launch(void* const* d_in, const int* in_sizes, int n_in,
                              void* d_out, int out_size) {
    const float* hid = (const float*)d_in[0];
    const float* rw  = (const float*)d_in[1];
    const int*   sel = (const int*)  d_in[2];
    const float* gw  = (const float*)d_in[3];
    const float* uw  = (const float*)d_in[4];
    const float* dw  = (const float*)d_in[5];
    float* out = (float*)d_out;

    void *p_xp, *p_act, *p_gh, *p_uh, *p_dh;
    cudaGetSymbolAddress(&p_xp,  g_xp);
    cudaGetSymbolAddress(&p_act, g_act);
    cudaGetSymbolAddress(&p_gh,  g_gate_h);
    cudaGetSymbolAddress(&p_uh,  g_up_h);
    cudaGetSymbolAddress(&p_dh,  g_down_h);

    cudaFuncSetAttribute(k_gemm1_mma, cudaFuncAttributeMaxDynamicSharedMemorySize, G1_SMEM);
    cudaFuncSetAttribute(k_gemm2_mma, cudaFuncAttributeMaxDynamicSharedMemorySize, G2_SMEM);

    // routing prep
    k_zero_counts<<<1, 32>>>();
    k_hist<<<R_ROWS / 256, 256>>>(sel);
    k_prep<<<1, 1>>>();
    k_scatter<<<R_ROWS / 256, 256>>>(sel, rw);

    // staging: gather+scale+fp16 A; straight scale+fp16 weight converts
    k_permute<<<R_ROWS, 256>>>(hid);
    {
        size_t n8 = (size_t)N_EXP * H_DIM * I_DIM / 8;
        int blocks = (int)((n8 + 255) / 256);
        k_convert<<<blocks, 256>>>(gw, (__half*)p_gh, n8);
        k_convert<<<blocks, 256>>>(uw, (__half*)p_uh, n8);
        k_convert<<<blocks, 256>>>(dw, (__half*)p_dh, n8);
    }

    int n4 = (T_TOK * H_DIM) / 4;
    k_zero_out<<<n4 / 256, 256>>>((float4*)out, n4);

    dim3 g1(MAX_TILES, I_DIM / BN1);   // 72 x 22
    k_gemm1_mma<<<g1, 256, G1_SMEM>>>((const __half*)p_xp, (const __half*)p_gh, (const __half*)p_uh);

    dim3 g2(MAX_TILES, H_DIM / BN2);   // 72 x 16
    k_gemm2_mma<<<g2, 256, G2_SMEM>>>((const __half*)p_act, (const __half*)p_dh, out);
}

// round 15
// speedup vs baseline: 1.1587x; 1.1587x over previous
#include <cuda_runtime.h>
#include <cuda_fp16.h>
#include <math.h>
#include <stdint.h>
#include <string.h>

// ---------------------------------------------------------------------------
// MoE grouped MLP via fp16 mma.sync m16n8k16 (R12 GEMM config).
// GEMM1: 128x64(x2 mats), 256 thr, 2 CTA/SM, A gathered via row index.
// GEMM2: 128x128, warp 32x64, 256 thr, 2 CTA/SM.
// Staging: one routing kernel, one hid convert, one merged weight convert.
// T=4096 H=2048 I=1408 E=8 K=2; rows = 8192.
// ---------------------------------------------------------------------------
#define T_TOK 4096
#define H_DIM 2048
#define I_DIM 1408
#define N_EXP 8
#define TOPK  2
#define R_ROWS (T_TOK * TOPK)
#define BM 128
#define MAX_TILES (R_ROWS / BM + N_EXP)   // 72

#define BK 32
#define STAGES 4
#define NK1 (H_DIM / BK)                   // 64
#define NK2 (I_DIM / BK)                   // 44

#define BN1 64
#define BN2 128

// A-tile SMEM: padded stride 40 halfs (conflict-free for ldmatrix)
#define SH 40
#define AS_H (BM * SH)                     // 5120 halfs = 10240 B
#define BT1_B (BK * BN1 * 2)               // 4096 B
#define BT2_B (BK * BN2 * 2)               // 8192 B
#define G1_SMEM (STAGES * (AS_H * 2 + 2 * BT1_B))   // 73728 B
#define G2_SMEM (STAGES * (AS_H * 2 + BT2_B))       // 73728 B

#define ACT_ROWS (R_ROWS + 128)

// static scaling: x*64, W*64, act*4096
#define S_IN   64.0f
#define DESC1  (1.0f / (64.0f * 64.0f))
#define S_ACT  4096.0f
#define DESC2  (1.0f / (4096.0f * 64.0f))

// ---- device-global scratch ----
__device__ int    g_tile_e[MAX_TILES];
__device__ int    g_tile_row0[MAX_TILES];
__device__ int    g_tile_rows[MAX_TILES];
__device__ int    g_num_tiles;
__device__ int    g_row_t[R_ROWS + 128];          // padded (tail tiles gather token 0)
__device__ float  g_row_p[R_ROWS];
__device__ __half g_hid_h[(size_t)T_TOK * H_DIM];            // scaled fp16 hidden
__device__ __half g_act[(size_t)ACT_ROWS * I_DIM];
__device__ __half g_gate_h[(size_t)N_EXP * H_DIM * I_DIM];   // [E][H][I]
__device__ __half g_up_h  [(size_t)N_EXP * H_DIM * I_DIM];
__device__ __half g_down_h[(size_t)N_EXP * I_DIM * H_DIM];   // [E][I][H]

// ---------------------------------------------------------------------------
__device__ __forceinline__ uint32_t h2_bits(__half2 h) {
    uint32_t u;
    memcpy(&u, &h, 4);
    return u;
}
__device__ __forceinline__ void cp16(void* dst, const void* src) {
    uint32_t d = (uint32_t)__cvta_generic_to_shared(dst);
    asm volatile("cp.async.cg.shared.global [%0], [%1], 16;" :: "r"(d), "l"(src) : "memory");
}
__device__ __forceinline__ void cp16s(uint32_t dst, const void* src) {
    asm volatile("cp.async.cg.shared.global [%0], [%1], 16;" :: "r"(dst), "l"(src) : "memory");
}
#define CP_COMMIT() asm volatile("cp.async.commit_group;" ::: "memory")
#define CP_WAIT2()  asm volatile("cp.async.wait_group 2;" ::: "memory")

#define MMA_F16(d, a, b0, b1)                                                \
    asm volatile("mma.sync.aligned.m16n8k16.row.col.f32.f16.f16.f32 "        \
        "{%0,%1,%2,%3}, {%4,%5,%6,%7}, {%8,%9}, {%0,%1,%2,%3};"              \
        : "+f"((d)[0]), "+f"((d)[1]), "+f"((d)[2]), "+f"((d)[3])             \
        : "r"((a)[0]), "r"((a)[1]), "r"((a)[2]), "r"((a)[3]),                \
          "r"(b0), "r"(b1))

#define LDSM4(r, addr)                                                        \
    asm volatile("ldmatrix.sync.aligned.m8n8.x4.shared.b16 {%0,%1,%2,%3}, [%4];" \
        : "=r"((r)[0]), "=r"((r)[1]), "=r"((r)[2]), "=r"((r)[3]) : "r"(addr))

#define LDSM4T(r, addr)                                                       \
    asm volatile("ldmatrix.sync.aligned.m8n8.x4.trans.shared.b16 {%0,%1,%2,%3}, [%4];" \
        : "=r"((r)[0]), "=r"((r)[1]), "=r"((r)[2]), "=r"((r)[3]) : "r"(addr))

#define REDV2(ptr, v0, v1)                                                    \
    asm volatile("red.global.add.v2.f32 [%0], {%1, %2};"                      \
        :: "l"(ptr), "f"(v0), "f"(v1) : "memory")

// ---------------------------------------------------------------------------
// single-kernel routing: histogram -> prefix+tiles -> scatter (one block)
// ---------------------------------------------------------------------------
__global__ void k_route(const int* __restrict__ sel, const float* __restrict__ rw) {
    __shared__ int cnt[N_EXP];
    __shared__ int cur[N_EXP];
    const int tid = threadIdx.x;                    // 256 threads

    if (tid < N_EXP) cnt[tid] = 0;
    if (tid < 128) g_row_t[R_ROWS + tid] = 0;       // pad: tail tiles gather token 0
    __syncthreads();

    for (int f = tid; f < R_ROWS; f += 256) {
        int t = f % T_TOK, k = f / T_TOK;
        atomicAdd(&cnt[sel[t * TOPK + k]], 1);
    }
    __syncthreads();

    if (tid == 0) {
        int off = 0, nt = 0;
        for (int e = 0; e < N_EXP; ++e) {
            int c = cnt[e];
            cur[e] = off;
            for (int r0 = 0; r0 < c; r0 += BM) {
                g_tile_e[nt] = e; g_tile_row0[nt] = off + r0;
                g_tile_rows[nt] = min(BM, c - r0); ++nt;
            }
            off += c;
        }
        g_num_tiles = nt;
    }
    __syncthreads();

    for (int f = tid; f < R_ROWS; f += 256) {
        int t = f % T_TOK, k = f / T_TOK;
        int e = sel[t * TOPK + k];
        int d = atomicAdd(&cur[e], 1);
        g_row_t[d] = t;
        g_row_p[d] = rw[t * TOPK + k];
    }
}

__global__ void k_zero_out(float4* __restrict__ out, int n4) {
    int i = blockIdx.x * blockDim.x + threadIdx.x;
    if (i < n4) out[i] = make_float4(0.f, 0.f, 0.f, 0.f);
}

// streaming convert: out[i] = half(in[i] * S_IN), 8 elems/thread
__global__ void k_convert(const float* __restrict__ in, __half* __restrict__ out,
                          size_t n8) {
    size_t i = (size_t)blockIdx.x * blockDim.x + threadIdx.x;
    if (i < n8) {
        const float4* src = (const float4*)in + 2 * i;
        float4 v0 = src[0], v1 = src[1];
        uint4 o;
        o.x = h2_bits(__floats2half2_rn(v0.x * S_IN, v0.y * S_IN));
        o.y = h2_bits(__floats2half2_rn(v0.z * S_IN, v0.w * S_IN));
        o.z = h2_bits(__floats2half2_rn(v1.x * S_IN, v1.y * S_IN));
        o.w = h2_bits(__floats2half2_rn(v1.z * S_IN, v1.w * S_IN));
        ((uint4*)out)[i] = o;
    }
}

// merged weight convert: grid.y selects tensor
__global__ void k_convert3(const float* __restrict__ gw, const float* __restrict__ uw,
                           const float* __restrict__ dw,
                           __half* g_out, __half* u_out, __half* d_out, size_t n8) {
    size_t i = (size_t)blockIdx.x * blockDim.x + threadIdx.x;
    if (i >= n8) return;
    const float* in; __half* out;
    if (blockIdx.y == 0)      { in = gw; out = g_out; }
    else if (blockIdx.y == 1) { in = uw; out = u_out; }
    else                      { in = dw; out = d_out; }
    const float4* src = (const float4*)in + 2 * i;
    float4 v0 = src[0], v1 = src[1];
    uint4 o;
    o.x = h2_bits(__floats2half2_rn(v0.x * S_IN, v0.y * S_IN));
    o.y = h2_bits(__floats2half2_rn(v0.z * S_IN, v0.w * S_IN));
    o.z = h2_bits(__floats2half2_rn(v1.x * S_IN, v1.y * S_IN));
    o.w = h2_bits(__floats2half2_rn(v1.z * S_IN, v1.w * S_IN));
    ((uint4*)out)[i] = o;
}

// ---------------------------------------------------------------------------
// GEMM1: act = silu(x @ gate^T) * (x @ up^T)
// 128x64 tiles, 256 threads = 8 warps (4M x 2N), warp 32x32 (x2 mats).
// A rows gathered from g_hid_h via g_row_t (index hoisted out of K loop).
// ---------------------------------------------------------------------------
__global__ __launch_bounds__(256, 2)
void k_gemm1_mma(const __half* __restrict__ xh,
                 const __half* __restrict__ gt,
                 const __half* __restrict__ ut) {
    const int tile = blockIdx.x;
    if (tile >= g_num_tiles) return;
    const int e    = g_tile_e[tile];
    const int row0 = g_tile_row0[tile];
    const int rows = g_tile_rows[tile];
    const int n0   = blockIdx.y * BN1;

    extern __shared__ __half sm[];
    __half* As = sm;
    const uint32_t su  = (uint32_t)__cvta_generic_to_shared(sm);
    const uint32_t bgu = su + STAGES * AS_H * 2;
    const uint32_t buu = bgu + STAGES * BT1_B;

    const int tid  = threadIdx.x;
    const int lane = tid & 31, wid = tid >> 5;
    const int wm = wid & 3, wn = wid >> 2;
    const int lg = lane >> 2, lt = lane & 3;

    const uint32_t aoff = (((lane & 7) + ((lane >> 3) & 1) * 8) * SH + (lane >> 4) * 8) * 2;
    const uint32_t blk_row  = (lane & 7) + ((lane >> 3) & 1) * 8;
    const uint32_t bxor     = lane & 7;
    const uint32_t bnc_base = wn * 4 + (lane >> 4);

    const __half* gte = gt + (size_t)e * H_DIM * I_DIM + n0;
    const __half* ute = ut + (size_t)e * H_DIM * I_DIM + n0;

    const int alr = tid >> 1, alc = (tid & 1) * 2;
    const int bk  = tid >> 3, bc = tid & 7;
    const uint32_t bsw = (uint32_t)(bk * 128 + ((bc ^ (bk & 7)) << 4));

    // indirect A row (hoisted gather index)
    const __half* arow_t = xh + (size_t)g_row_t[row0 + alr] * H_DIM;

    float accg[2][4][4], accu[2][4][4];
    #pragma unroll
    for (int a = 0; a < 2; ++a)
        #pragma unroll
        for (int b = 0; b < 4; ++b)
            #pragma unroll
            for (int c = 0; c < 4; ++c) { accg[a][b][c] = 0.f; accu[a][b][c] = 0.f; }

    #define G1_LOAD(s, ki) do {                                                   \
        int k0_ = (ki) * BK;                                                      \
        __half* as_ = As + (s) * AS_H;                                            \
        cp16(&as_[alr * SH + alc * 8],       arow_t + k0_ + alc * 8);             \
        cp16(&as_[alr * SH + (alc + 1) * 8], arow_t + k0_ + (alc + 1) * 8);       \
        cp16s(bgu + (s) * BT1_B + bsw, gte + (size_t)(k0_ + bk) * I_DIM + bc * 8); \
        cp16s(buu + (s) * BT1_B + bsw, ute + (size_t)(k0_ + bk) * I_DIM + bc * 8); \
    } while (0)

    G1_LOAD(0, 0); CP_COMMIT();
    G1_LOAD(1, 1); CP_COMMIT();
    G1_LOAD(2, 2); CP_COMMIT();

    int slot = 0;
    #pragma unroll 1
    for (int ki = 0; ki < NK1; ++ki) {
        CP_WAIT2();
        __syncthreads();
        if (ki + 3 < NK1) {
            int ns = slot + 3; if (ns >= STAGES) ns -= STAGES;
            G1_LOAD(ns, ki + 3);
        }
        CP_COMMIT();

        const uint32_t asb = su  + slot * AS_H * 2 + (wm * 32) * SH * 2 + aoff;
        const uint32_t bgs = bgu + slot * BT1_B;
        const uint32_t bus = buu + slot * BT1_B;
        #pragma unroll
        for (int ks = 0; ks < 2; ++ks) {
            const uint32_t kb2 = ks * 32;
            const uint32_t bkrow = (ks * 16 + blk_row) * 128;
            uint32_t af[2][4], bgr[8], bur[8];
            LDSM4(af[0], asb + kb2);
            LDSM4(af[1], asb + 16 * SH * 2 + kb2);
            LDSM4T(&bgr[0], bgs + bkrow + (((bnc_base + 0) ^ bxor) << 4));
            LDSM4T(&bgr[4], bgs + bkrow + (((bnc_base + 2) ^ bxor) << 4));
            LDSM4T(&bur[0], bus + bkrow + (((bnc_base + 0) ^ bxor) << 4));
            LDSM4T(&bur[4], bus + bkrow + (((bnc_base + 2) ^ bxor) << 4));
            #pragma unroll
            for (int nt = 0; nt < 4; ++nt) {
                #pragma unroll
                for (int mt = 0; mt < 2; ++mt) {
                    MMA_F16(accg[mt][nt], af[mt], bgr[2 * nt], bgr[2 * nt + 1]);
                    MMA_F16(accu[mt][nt], af[mt], bur[2 * nt], bur[2 * nt + 1]);
                }
            }
        }
        if (++slot == STAGES) slot = 0;
    }
    #undef G1_LOAD

    // epilogue: descale, silu(g)*u, rescale, store fp16
    #pragma unroll
    for (int mt = 0; mt < 2; ++mt) {
        #pragma unroll
        for (int half = 0; half < 2; ++half) {
            int m = wm * 32 + mt * 16 + lg + half * 8;
            if (m < rows) {
                __half* dst = g_act + (size_t)(row0 + m) * I_DIM + n0 + wn * 32;
                #pragma unroll
                for (int nt = 0; nt < 4; ++nt) {
                    float g0 = accg[mt][nt][half * 2 + 0] * DESC1;
                    float u0 = accu[mt][nt][half * 2 + 0] * DESC1;
                    float g1 = accg[mt][nt][half * 2 + 1] * DESC1;
                    float u1 = accu[mt][nt][half * 2 + 1] * DESC1;
                    float a0 = (g0 / (1.f + __expf(-g0))) * u0 * S_ACT;
                    float a1 = (g1 / (1.f + __expf(-g1))) * u1 * S_ACT;
                    *(__half2*)(dst + nt * 8 + 2 * lt) = __floats2half2_rn(a0, a1);
                }
            }
        }
    }
}

// ---------------------------------------------------------------------------
// GEMM2: out[t] += p * descale * (act @ down^T)
// 128x128 tiles, 256 threads = 8 warps (4M x 2N), warp tile 32x64.
// ---------------------------------------------------------------------------
__global__ __launch_bounds__(256, 2)
void k_gemm2_mma(const __half* __restrict__ act,
                 const __half* __restrict__ dt,
                 float* __restrict__ out) {
    const int tile = blockIdx.x;
    if (tile >= g_num_tiles) return;
    const int e    = g_tile_e[tile];
    const int row0 = g_tile_row0[tile];
    const int rows = g_tile_rows[tile];
    const int n0   = blockIdx.y * BN2;

    extern __shared__ __half sm[];
    __half* As = sm;
    const uint32_t su  = (uint32_t)__cvta_generic_to_shared(sm);
    const uint32_t bsu = su + STAGES * AS_H * 2;

    const int tid  = threadIdx.x;
    const int lane = tid & 31, wid = tid >> 5;
    const int wm = wid & 3, wn = wid >> 2;       // 4M x 2N
    const int lg = lane >> 2, lt = lane & 3;

    const uint32_t aoff = (((lane & 7) + ((lane >> 3) & 1) * 8) * SH + (lane >> 4) * 8) * 2;
    const uint32_t blk_row  = (lane & 7) + ((lane >> 3) & 1) * 8;
    const uint32_t bxor     = lane & 7;
    const uint32_t bnc_base = wn * 8 + (lane >> 4);   // warp covers 8 chunks (64 cols)

    const __half* arow = act + (size_t)row0 * I_DIM;
    const __half* dte  = dt + (size_t)e * I_DIM * H_DIM + n0;

    const int alr = tid >> 1, alc = (tid & 1) * 2;   // A: 2 cp16/thread
    const int bk  = tid >> 3, bc = tid & 7;          // B: 2 cp16/thread (16 chunks/row)
    const uint32_t bsw = (uint32_t)(bk * 256 + ((bc ^ (bk & 7)) << 4));

    float acc[2][8][4];
    #pragma unroll
    for (int a = 0; a < 2; ++a)
        #pragma unroll
        for (int b = 0; b < 8; ++b)
            #pragma unroll
            for (int c = 0; c < 4; ++c) acc[a][b][c] = 0.f;

    #define G2_LOAD(s, ki) do {                                                   \
        int k0_ = (ki) * BK;                                                      \
        __half* as_ = As + (s) * AS_H;                                            \
        cp16(&as_[alr * SH + alc * 8],       arow + (size_t)alr * I_DIM + k0_ + alc * 8);      \
        cp16(&as_[alr * SH + (alc + 1) * 8], arow + (size_t)alr * I_DIM + k0_ + (alc + 1) * 8);\
        cp16s(bsu + (s) * BT2_B + bsw,       dte + (size_t)(k0_ + bk) * H_DIM + bc * 8);       \
        cp16s(bsu + (s) * BT2_B + bsw + 128, dte + (size_t)(k0_ + bk) * H_DIM + (bc + 8) * 8); \
    } while (0)

    G2_LOAD(0, 0); CP_COMMIT();
    G2_LOAD(1, 1); CP_COMMIT();
    G2_LOAD(2, 2); CP_COMMIT();

    int slot = 0;
    #pragma unroll 1
    for (int ki = 0; ki < NK2; ++ki) {
        CP_WAIT2();
        __syncthreads();
        if (ki + 3 < NK2) {
            int ns = slot + 3; if (ns >= STAGES) ns -= STAGES;
            G2_LOAD(ns, ki + 3);
        }
        CP_COMMIT();

        const uint32_t asb = su  + slot * AS_H * 2 + (wm * 32) * SH * 2 + aoff;
        const uint32_t bss = bsu + slot * BT2_B;
        #pragma unroll
        for (int ks = 0; ks < 2; ++ks) {
            const uint32_t kb2 = ks * 32;
            const uint32_t bkrow = (ks * 16 + blk_row) * 256;
            uint32_t af[2][4], br[16];
            LDSM4(af[0], asb + kb2);
            LDSM4(af[1], asb + 16 * SH * 2 + kb2);
            LDSM4T(&br[0],  bss + bkrow + (((bnc_base + 0) ^ bxor) << 4));
            LDSM4T(&br[4],  bss + bkrow + (((bnc_base + 2) ^ bxor) << 4));
            LDSM4T(&br[8],  bss + bkrow + (((bnc_base + 4) ^ bxor) << 4));
            LDSM4T(&br[12], bss + bkrow + (((bnc_base + 6) ^ bxor) << 4));
            #pragma unroll
            for (int nt = 0; nt < 8; ++nt) {
                #pragma unroll
                for (int mt = 0; mt < 2; ++mt)
                    MMA_F16(acc[mt][nt], af[mt], br[2 * nt], br[2 * nt + 1]);
            }
        }
        if (++slot == STAGES) slot = 0;
    }
    #undef G2_LOAD

    // epilogue: weighted vector reduce-add with descale
    #pragma unroll
    for (int mt = 0; mt < 2; ++mt) {
        #pragma unroll
        for (int half = 0; half < 2; ++half) {
            int m = wm * 32 + mt * 16 + lg + half * 8;
            if (m < rows) {
                float p = g_row_p[row0 + m] * DESC2;
                int   t = g_row_t[row0 + m];
                float* dst = out + (size_t)t * H_DIM + n0 + wn * 64;
                #pragma unroll
                for (int nt = 0; nt < 8; ++nt) {
                    REDV2(dst + nt * 8 + 2 * lt,
                          acc[mt][nt][half * 2 + 0] * p,
                          acc[mt][nt][half * 2 + 1] * p);
                }
            }
        }
    }
}

// ---------------------------------------------------------------------------
extern "C" void kernel_launch(void* const* d_in, const int* in_sizes, int n_in,
                              void* d_out, int out_size) {
    const float* hid = (const float*)d_in[0];
    const float* rw  = (const float*)d_in[1];
    const int*   sel = (const int*)  d_in[2];
    const float* gw  = (const float*)d_in[3];
    const float* uw  = (const float*)d_in[4];
    const float* dw  = (const float*)d_in[5];
    float* out = (float*)d_out;

    void *p_xh, *p_act, *p_gh, *p_uh, *p_dh;
    cudaGetSymbolAddress(&p_xh,  g_hid_h);
    cudaGetSymbolAddress(&p_act, g_act);
    cudaGetSymbolAddress(&p_gh,  g_gate_h);
    cudaGetSymbolAddress(&p_uh,  g_up_h);
    cudaGetSymbolAddress(&p_dh,  g_down_h);

    cudaFuncSetAttribute(k_gemm1_mma, cudaFuncAttributeMaxDynamicSharedMemorySize, G1_SMEM);
    cudaFuncSetAttribute(k_gemm2_mma, cudaFuncAttributeMaxDynamicSharedMemorySize, G2_SMEM);

    // routing (single launch)
    k_route<<<1, 256>>>(sel, rw);

    // staging: convert hid once; merged weight convert
    {
        size_t nh8 = (size_t)T_TOK * H_DIM / 8;              // 1048576
        k_convert<<<(int)(nh8 / 256), 256>>>(hid, (__half*)p_xh, nh8);
        size_t nw8 = (size_t)N_EXP * H_DIM * I_DIM / 8;      // 2883584
        dim3 gc((unsigned)((nw8 + 255) / 256), 3);
        k_convert3<<<gc, 256>>>(gw, uw, dw,
                                (__half*)p_gh, (__half*)p_uh, (__half*)p_dh, nw8);
    }

    int n4 = (T_TOK * H_DIM) / 4;
    k_zero_out<<<n4 / 256, 256>>>((float4*)out, n4);

    dim3 g1(MAX_TILES, I_DIM / BN1);   // 72 x 22
    k_gemm1_mma<<<g1, 256, G1_SMEM>>>((const __half*)p_xh, (const __half*)p_gh, (const __half*)p_uh);

    dim3 g2(MAX_TILES, H_DIM / BN2);   // 72 x 16
    k_gemm2_mma<<<g2, 256, G2_SMEM>>>((const __half*)p_act, (const __half*)p_dh, out);
}

// round 16
// speedup vs baseline: 1.1863x; 1.0237x over previous
#include <cuda_runtime.h>
#include <cuda_fp16.h>
#include <math.h>
#include <stdint.h>
#include <string.h>

// ---------------------------------------------------------------------------
// MoE grouped MLP via fp16 mma.sync m16n8k16 (R12 GEMM config, R14 gather).
// Staging fully fused into ONE kernel (route + converts + zero) so the
// routing/zero/hid work hides under the DRAM-bound weight convert stream.
// T=4096 H=2048 I=1408 E=8 K=2; rows = 8192.
// ---------------------------------------------------------------------------
#define T_TOK 4096
#define H_DIM 2048
#define I_DIM 1408
#define N_EXP 8
#define TOPK  2
#define R_ROWS (T_TOK * TOPK)
#define BM 128
#define MAX_TILES (R_ROWS / BM + N_EXP)   // 72

#define BK 32
#define STAGES 4
#define NK1 (H_DIM / BK)                   // 64
#define NK2 (I_DIM / BK)                   // 44

#define BN1 64
#define BN2 128

#define SH 40
#define AS_H (BM * SH)                     // 5120 halfs = 10240 B
#define BT1_B (BK * BN1 * 2)               // 4096 B
#define BT2_B (BK * BN2 * 2)               // 8192 B
#define G1_SMEM (STAGES * (AS_H * 2 + 2 * BT1_B))   // 73728 B
#define G2_SMEM (STAGES * (AS_H * 2 + BT2_B))       // 73728 B

#define ACT_ROWS (R_ROWS + 128)

// static scaling: x*64, W*64, act*4096
#define S_IN   64.0f
#define DESC1  (1.0f / (64.0f * 64.0f))
#define S_ACT  4096.0f
#define DESC2  (1.0f / (4096.0f * 64.0f))

// staging grid partition (all blocks 256 threads)
#define NW8   ((size_t)N_EXP * H_DIM * I_DIM / 8)   // 2883584
#define NH8   ((size_t)T_TOK * H_DIM / 8)           // 1048576
#define NZ4   ((size_t)T_TOK * H_DIM / 4)           // 2097152
#define BLK_W ((int)(NW8 / 256))                    // 11264 per weight tensor
#define BLK_H ((int)(NH8 / 256))                    // 4096
#define BLK_Z ((int)(NZ4 / 256))                    // 8192
#define STAGE_BLOCKS (1 + BLK_H + BLK_Z + 3 * BLK_W)   // 46081

// ---- device-global scratch ----
__device__ int    g_tile_e[MAX_TILES];
__device__ int    g_tile_row0[MAX_TILES];
__device__ int    g_tile_rows[MAX_TILES];
__device__ int    g_num_tiles;
__device__ int    g_row_t[R_ROWS + 128];          // padded (tail tiles gather token 0)
__device__ float  g_row_p[R_ROWS];
__device__ __half g_hid_h[(size_t)T_TOK * H_DIM];
__device__ __half g_act[(size_t)ACT_ROWS * I_DIM];
__device__ __half g_gate_h[(size_t)N_EXP * H_DIM * I_DIM];   // [E][H][I]
__device__ __half g_up_h  [(size_t)N_EXP * H_DIM * I_DIM];
__device__ __half g_down_h[(size_t)N_EXP * I_DIM * H_DIM];   // [E][I][H]

// ---------------------------------------------------------------------------
__device__ __forceinline__ uint32_t h2_bits(__half2 h) {
    uint32_t u;
    memcpy(&u, &h, 4);
    return u;
}
__device__ __forceinline__ void cp16(void* dst, const void* src) {
    uint32_t d = (uint32_t)__cvta_generic_to_shared(dst);
    asm volatile("cp.async.cg.shared.global [%0], [%1], 16;" :: "r"(d), "l"(src) : "memory");
}
__device__ __forceinline__ void cp16s(uint32_t dst, const void* src) {
    asm volatile("cp.async.cg.shared.global [%0], [%1], 16;" :: "r"(dst), "l"(src) : "memory");
}
#define CP_COMMIT() asm volatile("cp.async.commit_group;" ::: "memory")
#define CP_WAIT2()  asm volatile("cp.async.wait_group 2;" ::: "memory")

#define MMA_F16(d, a, b0, b1)                                                \
    asm volatile("mma.sync.aligned.m16n8k16.row.col.f32.f16.f16.f32 "        \
        "{%0,%1,%2,%3}, {%4,%5,%6,%7}, {%8,%9}, {%0,%1,%2,%3};"              \
        : "+f"((d)[0]), "+f"((d)[1]), "+f"((d)[2]), "+f"((d)[3])             \
        : "r"((a)[0]), "r"((a)[1]), "r"((a)[2]), "r"((a)[3]),                \
          "r"(b0), "r"(b1))

#define LDSM4(r, addr)                                                        \
    asm volatile("ldmatrix.sync.aligned.m8n8.x4.shared.b16 {%0,%1,%2,%3}, [%4];" \
        : "=r"((r)[0]), "=r"((r)[1]), "=r"((r)[2]), "=r"((r)[3]) : "r"(addr))

#define LDSM4T(r, addr)                                                       \
    asm volatile("ldmatrix.sync.aligned.m8n8.x4.trans.shared.b16 {%0,%1,%2,%3}, [%4];" \
        : "=r"((r)[0]), "=r"((r)[1]), "=r"((r)[2]), "=r"((r)[3]) : "r"(addr))

#define REDV2(ptr, v0, v1)                                                    \
    asm volatile("red.global.add.v2.f32 [%0], {%1, %2};"                      \
        :: "l"(ptr), "f"(v0), "f"(v1) : "memory")

// ---------------------------------------------------------------------------
// fused staging kernel: block 0 = routing; then hid convert; then zero out;
// then 3 weight-tensor converts. 256 threads per block.
// ---------------------------------------------------------------------------
__device__ __forceinline__ void cvt8(const float* __restrict__ in,
                                     __half* __restrict__ out, size_t i) {
    const float4* src = (const float4*)in + 2 * i;
    float4 v0 = src[0], v1 = src[1];
    uint4 o;
    o.x = h2_bits(__floats2half2_rn(v0.x * S_IN, v0.y * S_IN));
    o.y = h2_bits(__floats2half2_rn(v0.z * S_IN, v0.w * S_IN));
    o.z = h2_bits(__floats2half2_rn(v1.x * S_IN, v1.y * S_IN));
    o.w = h2_bits(__floats2half2_rn(v1.z * S_IN, v1.w * S_IN));
    ((uint4*)out)[i] = o;
}

__global__ void k_stage(const int* __restrict__ sel, const float* __restrict__ rw,
                        const float* __restrict__ hid,
                        const float* __restrict__ gw, const float* __restrict__ uw,
                        const float* __restrict__ dw, float4* __restrict__ out) {
    const int bid = blockIdx.x;
    const int tid = threadIdx.x;

    if (bid == 0) {
        // ---- routing: histogram -> prefix+tiles -> scatter ----
        __shared__ int cnt[N_EXP];
        __shared__ int cur[N_EXP];
        if (tid < N_EXP) cnt[tid] = 0;
        if (tid < 128) g_row_t[R_ROWS + tid] = 0;
        __syncthreads();
        for (int f = tid; f < R_ROWS; f += 256) {
            int t = f % T_TOK, k = f / T_TOK;
            atomicAdd(&cnt[sel[t * TOPK + k]], 1);
        }
        __syncthreads();
        if (tid == 0) {
            int off = 0, nt = 0;
            for (int e = 0; e < N_EXP; ++e) {
                int c = cnt[e];
                cur[e] = off;
                for (int r0 = 0; r0 < c; r0 += BM) {
                    g_tile_e[nt] = e; g_tile_row0[nt] = off + r0;
                    g_tile_rows[nt] = min(BM, c - r0); ++nt;
                }
                off += c;
            }
            g_num_tiles = nt;
        }
        __syncthreads();
        for (int f = tid; f < R_ROWS; f += 256) {
            int t = f % T_TOK, k = f / T_TOK;
            int e = sel[t * TOPK + k];
            int d = atomicAdd(&cur[e], 1);
            g_row_t[d] = t;
            g_row_p[d] = rw[t * TOPK + k];
        }
        return;
    }
    int idx = bid - 1;
    if (idx < BLK_H) {
        // ---- hid convert ----
        cvt8(hid, g_hid_h, (size_t)idx * 256 + tid);
        return;
    }
    idx -= BLK_H;
    if (idx < BLK_Z) {
        // ---- zero output ----
        out[(size_t)idx * 256 + tid] = make_float4(0.f, 0.f, 0.f, 0.f);
        return;
    }
    idx -= BLK_Z;
    // ---- weight converts ----
    const int tensor = idx / BLK_W;
    const size_t i = (size_t)(idx % BLK_W) * 256 + tid;
    if (tensor == 0)      cvt8(gw, g_gate_h, i);
    else if (tensor == 1) cvt8(uw, g_up_h, i);
    else                  cvt8(dw, g_down_h, i);
}

// ---------------------------------------------------------------------------
// GEMM1: act = silu(x @ gate^T) * (x @ up^T)
// 128x64 tiles, 256 threads = 8 warps (4M x 2N), warp 32x32 (x2 mats).
// A rows gathered from g_hid_h via g_row_t (index hoisted out of K loop).
// ---------------------------------------------------------------------------
__global__ __launch_bounds__(256, 2)
void k_gemm1_mma(const __half* __restrict__ xh,
                 const __half* __restrict__ gt,
                 const __half* __restrict__ ut) {
    const int tile = blockIdx.x;
    if (tile >= g_num_tiles) return;
    const int e    = g_tile_e[tile];
    const int row0 = g_tile_row0[tile];
    const int rows = g_tile_rows[tile];
    const int n0   = blockIdx.y * BN1;

    extern __shared__ __half sm[];
    __half* As = sm;
    const uint32_t su  = (uint32_t)__cvta_generic_to_shared(sm);
    const uint32_t bgu = su + STAGES * AS_H * 2;
    const uint32_t buu = bgu + STAGES * BT1_B;

    const int tid  = threadIdx.x;
    const int lane = tid & 31, wid = tid >> 5;
    const int wm = wid & 3, wn = wid >> 2;
    const int lg = lane >> 2, lt = lane & 3;

    const uint32_t aoff = (((lane & 7) + ((lane >> 3) & 1) * 8) * SH + (lane >> 4) * 8) * 2;
    const uint32_t blk_row  = (lane & 7) + ((lane >> 3) & 1) * 8;
    const uint32_t bxor     = lane & 7;
    const uint32_t bnc_base = wn * 4 + (lane >> 4);

    const __half* gte = gt + (size_t)e * H_DIM * I_DIM + n0;
    const __half* ute = ut + (size_t)e * H_DIM * I_DIM + n0;

    const int alr = tid >> 1, alc = (tid & 1) * 2;
    const int bk  = tid >> 3, bc = tid & 7;
    const uint32_t bsw = (uint32_t)(bk * 128 + ((bc ^ (bk & 7)) << 4));

    const __half* arow_t = xh + (size_t)g_row_t[row0 + alr] * H_DIM;

    float accg[2][4][4], accu[2][4][4];
    #pragma unroll
    for (int a = 0; a < 2; ++a)
        #pragma unroll
        for (int b = 0; b < 4; ++b)
            #pragma unroll
            for (int c = 0; c < 4; ++c) { accg[a][b][c] = 0.f; accu[a][b][c] = 0.f; }

    #define G1_LOAD(s, ki) do {                                                   \
        int k0_ = (ki) * BK;                                                      \
        __half* as_ = As + (s) * AS_H;                                            \
        cp16(&as_[alr * SH + alc * 8],       arow_t + k0_ + alc * 8);             \
        cp16(&as_[alr * SH + (alc + 1) * 8], arow_t + k0_ + (alc + 1) * 8);       \
        cp16s(bgu + (s) * BT1_B + bsw, gte + (size_t)(k0_ + bk) * I_DIM + bc * 8); \
        cp16s(buu + (s) * BT1_B + bsw, ute + (size_t)(k0_ + bk) * I_DIM + bc * 8); \
    } while (0)

    G1_LOAD(0, 0); CP_COMMIT();
    G1_LOAD(1, 1); CP_COMMIT();
    G1_LOAD(2, 2); CP_COMMIT();

    int slot = 0;
    #pragma unroll 1
    for (int ki = 0; ki < NK1; ++ki) {
        CP_WAIT2();
        __syncthreads();
        if (ki + 3 < NK1) {
            int ns = slot + 3; if (ns >= STAGES) ns -= STAGES;
            G1_LOAD(ns, ki + 3);
        }
        CP_COMMIT();

        const uint32_t asb = su  + slot * AS_H * 2 + (wm * 32) * SH * 2 + aoff;
        const uint32_t bgs = bgu + slot * BT1_B;
        const uint32_t bus = buu + slot * BT1_B;
        #pragma unroll
        for (int ks = 0; ks < 2; ++ks) {
            const uint32_t kb2 = ks * 32;
            const uint32_t bkrow = (ks * 16 + blk_row) * 128;
            uint32_t af[2][4], bgr[8], bur[8];
            LDSM4(af[0], asb + kb2);
            LDSM4(af[1], asb + 16 * SH * 2 + kb2);
            LDSM4T(&bgr[0], bgs + bkrow + (((bnc_base + 0) ^ bxor) << 4));
            LDSM4T(&bgr[4], bgs + bkrow + (((bnc_base + 2) ^ bxor) << 4));
            LDSM4T(&bur[0], bus + bkrow + (((bnc_base + 0) ^ bxor) << 4));
            LDSM4T(&bur[4], bus + bkrow + (((bnc_base + 2) ^ bxor) << 4));
            #pragma unroll
            for (int nt = 0; nt < 4; ++nt) {
                #pragma unroll
                for (int mt = 0; mt < 2; ++mt) {
                    MMA_F16(accg[mt][nt], af[mt], bgr[2 * nt], bgr[2 * nt + 1]);
                    MMA_F16(accu[mt][nt], af[mt], bur[2 * nt], bur[2 * nt + 1]);
                }
            }
        }
        if (++slot == STAGES) slot = 0;
    }
    #undef G1_LOAD

    #pragma unroll
    for (int mt = 0; mt < 2; ++mt) {
        #pragma unroll
        for (int half = 0; half < 2; ++half) {
            int m = wm * 32 + mt * 16 + lg + half * 8;
            if (m < rows) {
                __half* dst = g_act + (size_t)(row0 + m) * I_DIM + n0 + wn * 32;
                #pragma unroll
                for (int nt = 0; nt < 4; ++nt) {
                    float g0 = accg[mt][nt][half * 2 + 0] * DESC1;
                    float u0 = accu[mt][nt][half * 2 + 0] * DESC1;
                    float g1 = accg[mt][nt][half * 2 + 1] * DESC1;
                    float u1 = accu[mt][nt][half * 2 + 1] * DESC1;
                    float a0 = (g0 / (1.f + __expf(-g0))) * u0 * S_ACT;
                    float a1 = (g1 / (1.f + __expf(-g1))) * u1 * S_ACT;
                    *(__half2*)(dst + nt * 8 + 2 * lt) = __floats2half2_rn(a0, a1);
                }
            }
        }
    }
}

// ---------------------------------------------------------------------------
// GEMM2: out[t] += p * descale * (act @ down^T)
// 128x128 tiles, 256 threads = 8 warps (4M x 2N), warp tile 32x64.
// ---------------------------------------------------------------------------
__global__ __launch_bounds__(256, 2)
void k_gemm2_mma(const __half* __restrict__ act,
                 const __half* __restrict__ dt,
                 float* __restrict__ out) {
    const int tile = blockIdx.x;
    if (tile >= g_num_tiles) return;
    const int e    = g_tile_e[tile];
    const int row0 = g_tile_row0[tile];
    const int rows = g_tile_rows[tile];
    const int n0   = blockIdx.y * BN2;

    extern __shared__ __half sm[];
    __half* As = sm;
    const uint32_t su  = (uint32_t)__cvta_generic_to_shared(sm);
    const uint32_t bsu = su + STAGES * AS_H * 2;

    const int tid  = threadIdx.x;
    const int lane = tid & 31, wid = tid >> 5;
    const int wm = wid & 3, wn = wid >> 2;
    const int lg = lane >> 2, lt = lane & 3;

    const uint32_t aoff = (((lane & 7) + ((lane >> 3) & 1) * 8) * SH + (lane >> 4) * 8) * 2;
    const uint32_t blk_row  = (lane & 7) + ((lane >> 3) & 1) * 8;
    const uint32_t bxor     = lane & 7;
    const uint32_t bnc_base = wn * 8 + (lane >> 4);

    const __half* arow = act + (size_t)row0 * I_DIM;
    const __half* dte  = dt + (size_t)e * I_DIM * H_DIM + n0;

    const int alr = tid >> 1, alc = (tid & 1) * 2;
    const int bk  = tid >> 3, bc = tid & 7;
    const uint32_t bsw = (uint32_t)(bk * 256 + ((bc ^ (bk & 7)) << 4));

    float acc[2][8][4];
    #pragma unroll
    for (int a = 0; a < 2; ++a)
        #pragma unroll
        for (int b = 0; b < 8; ++b)
            #pragma unroll
            for (int c = 0; c < 4; ++c) acc[a][b][c] = 0.f;

    #define G2_LOAD(s, ki) do {                                                   \
        int k0_ = (ki) * BK;                                                      \
        __half* as_ = As + (s) * AS_H;                                            \
        cp16(&as_[alr * SH + alc * 8],       arow + (size_t)alr * I_DIM + k0_ + alc * 8);      \
        cp16(&as_[alr * SH + (alc + 1) * 8], arow + (size_t)alr * I_DIM + k0_ + (alc + 1) * 8);\
        cp16s(bsu + (s) * BT2_B + bsw,       dte + (size_t)(k0_ + bk) * H_DIM + bc * 8);       \
        cp16s(bsu + (s) * BT2_B + bsw + 128, dte + (size_t)(k0_ + bk) * H_DIM + (bc + 8) * 8); \
    } while (0)

    G2_LOAD(0, 0); CP_COMMIT();
    G2_LOAD(1, 1); CP_COMMIT();
    G2_LOAD(2, 2); CP_COMMIT();

    int slot = 0;
    #pragma unroll 1
    for (int ki = 0; ki < NK2; ++ki) {
        CP_WAIT2();
        __syncthreads();
        if (ki + 3 < NK2) {
            int ns = slot + 3; if (ns >= STAGES) ns -= STAGES;
            G2_LOAD(ns, ki + 3);
        }
        CP_COMMIT();

        const uint32_t asb = su  + slot * AS_H * 2 + (wm * 32) * SH * 2 + aoff;
        const uint32_t bss = bsu + slot * BT2_B;
        #pragma unroll
        for (int ks = 0; ks < 2; ++ks) {
            const uint32_t kb2 = ks * 32;
            const uint32_t bkrow = (ks * 16 + blk_row) * 256;
            uint32_t af[2][4], br[16];
            LDSM4(af[0], asb + kb2);
            LDSM4(af[1], asb + 16 * SH * 2 + kb2);
            LDSM4T(&br[0],  bss + bkrow + (((bnc_base + 0) ^ bxor) << 4));
            LDSM4T(&br[4],  bss + bkrow + (((bnc_base + 2) ^ bxor) << 4));
            LDSM4T(&br[8],  bss + bkrow + (((bnc_base + 4) ^ bxor) << 4));
            LDSM4T(&br[12], bss + bkrow + (((bnc_base + 6) ^ bxor) << 4));
            #pragma unroll
            for (int nt = 0; nt < 8; ++nt) {
                #pragma unroll
                for (int mt = 0; mt < 2; ++mt)
                    MMA_F16(acc[mt][nt], af[mt], br[2 * nt], br[2 * nt + 1]);
            }
        }
        if (++slot == STAGES) slot = 0;
    }
    #undef G2_LOAD

    #pragma unroll
    for (int mt = 0; mt < 2; ++mt) {
        #pragma unroll
        for (int half = 0; half < 2; ++half) {
            int m = wm * 32 + mt * 16 + lg + half * 8;
            if (m < rows) {
                float p = g_row_p[row0 + m] * DESC2;
                int   t = g_row_t[row0 + m];
                float* dst = out + (size_t)t * H_DIM + n0 + wn * 64;
                #pragma unroll
                for (int nt = 0; nt < 8; ++nt) {
                    REDV2(dst + nt * 8 + 2 * lt,
                          acc[mt][nt][half * 2 + 0] * p,
                          acc[mt][nt][half * 2 + 1] * p);
                }
            }
        }
    }
}

// ---------------------------------------------------------------------------
extern "C" void kernel_launch(void* const* d_in, const int* in_sizes, int n_in,
                              void* d_out, int out_size) {
    const float* hid = (const float*)d_in[0];
    const float* rw  = (const float*)d_in[1];
    const int*   sel = (const int*)  d_in[2];
    const float* gw  = (const float*)d_in[3];
    const float* uw  = (const float*)d_in[4];
    const float* dw  = (const float*)d_in[5];
    float* out = (float*)d_out;

    void *p_xh, *p_act, *p_gh, *p_uh, *p_dh;
    cudaGetSymbolAddress(&p_xh,  g_hid_h);
    cudaGetSymbolAddress(&p_act, g_act);
    cudaGetSymbolAddress(&p_gh,  g_gate_h);
    cudaGetSymbolAddress(&p_uh,  g_up_h);
    cudaGetSymbolAddress(&p_dh,  g_down_h);

    cudaFuncSetAttribute(k_gemm1_mma, cudaFuncAttributeMaxDynamicSharedMemorySize, G1_SMEM);
    cudaFuncSetAttribute(k_gemm2_mma, cudaFuncAttributeMaxDynamicSharedMemorySize, G2_SMEM);

    // fused staging: routing + hid convert + zero out + weight converts
    k_stage<<<STAGE_BLOCKS, 256>>>(sel, rw, hid, gw, uw, dw, (float4*)out);

    dim3 g1(MAX_TILES, I_DIM / BN1);   // 72 x 22
    k_gemm1_mma<<<g1, 256, G1_SMEM>>>((const __half*)p_xh, (const __half*)p_gh, (const __half*)p_uh);

    dim3 g2(MAX_TILES, H_DIM / BN2);   // 72 x 16
    k_gemm2_mma<<<g2, 256, G2_SMEM>>>((const __half*)p_act, (const __half*)p_dh, out);
}